// round 9
// baseline (speedup 1.0000x reference)
#include <cuda_runtime.h>
#include <math.h>
#include <stdint.h>

#define FN 360
#define BGRAPH 128
#define NNODE (FN*BGRAPH)
#define NEDGE 1000000
#define CCH 128
#define TRI 64980
#define D1 65364
#define ZP 65376
#define H1 512
#define H2 256
#define EPSV 1e-5f
#define PADK 136
#define AP 384

// ---------------- scratch ----------------
__device__ __align__(16) float g_dinv[NNODE];
__device__ __align__(16) float g_A[(size_t)BGRAPH*AP*AP];     // interleaved k
__device__ __align__(16) float g_xr[(size_t)NNODE*AP];        // interleaved k
__device__ __align__(16) float g_wr[(size_t)3*CCH*AP];        // W^T [cout][cin ilv]
__device__ __align__(16) float g_h[(size_t)BGRAPH*CCH*AP];    // h^T [b][c][j ilv]
__device__ __align__(16) float g_xs1[(size_t)NNODE*CCH];      // interleaved channels
__device__ __align__(16) float g_xs2[(size_t)NNODE*CCH];
__device__ __align__(16) float g_xs3[(size_t)NNODE*CCH];
__device__ __align__(16) float g_z[(size_t)BGRAPH*ZP];        // interleaved cols
__device__ __align__(16) float g_hpool[BGRAPH*384];
__device__ __align__(16) float g_a1[BGRAPH*H1];
__device__ __align__(16) float g_a2[BGRAPH*H2];
__device__ __align__(16) float g_a3[BGRAPH*H2];

// ---------------- helpers ----------------
__device__ __forceinline__ uint32_t f2tf(float f) {
    uint32_t u; asm("cvt.rna.tf32.f32 %0, %1;" : "=r"(u) : "f"(f)); return u;
}
__device__ __forceinline__ float rndtf(float f) { return __uint_as_float(f2tf(f)); }
// interleave within 8-groups: orig col c -> storage pos, so that a float2 at
// pos 2*kt yields original (kt, kt+4).
__device__ __forceinline__ int ilv8(int c) { return (c & ~7) + 2*(c & 3) + ((c >> 2) & 1); }
__device__ __forceinline__ int pl8(int j)  { return 2*(j & 3) + (j >> 2); }      // within group
__device__ __forceinline__ int orig8(int p){ return (p & ~7) + ((p & 1) << 2) + ((p >> 1) & 3); }
__device__ __forceinline__ float fast_tanh(float x) {
    float e = __expf(2.0f*x);
    return 1.0f - __fdividef(2.0f, e + 1.0f);
}
__device__ __forceinline__ uint32_t s2u(const void* p) {
    uint32_t a;
    asm("{ .reg .u64 t; cvta.to.shared.u64 t, %1; cvt.u32.u64 %0, t; }" : "=r"(a) : "l"(p));
    return a;
}
__device__ __forceinline__ void cpa16(uint32_t d, const void* g) {
    asm volatile("cp.async.cg.shared.global [%0], [%1], 16;" :: "r"(d), "l"(g));
}
__device__ __forceinline__ void mma8(float* c, const uint32_t* a, const uint32_t* b) {
    asm volatile("mma.sync.aligned.m16n8k8.row.col.f32.tf32.tf32.f32 "
        "{%0,%1,%2,%3}, {%4,%5,%6,%7}, {%8,%9}, {%0,%1,%2,%3};"
        : "+f"(c[0]), "+f"(c[1]), "+f"(c[2]), "+f"(c[3])
        : "r"(a[0]), "r"(a[1]), "r"(a[2]), "r"(a[3]), "r"(b[0]), "r"(b[1]));
}

// ---------------- prep ----------------
// W^T, rounded, k interleaved: g_wr[(w*CCH + cout)*AP + grp*8 + pl8(j)] = W[grp*8+j][cout]
__global__ void k_prep(const float* __restrict__ Wc1, const float* __restrict__ Wc2,
                       const float* __restrict__ Wc3) {
    int i = blockIdx.x*blockDim.x + threadIdx.x;
    if (i >= 3*CCH*(AP/8)) return;
    int w = i / (CCH*(AP/8));
    int r = (i / (AP/8)) % CCH;
    int grp = i % (AP/8);
    const float* W = (w==0) ? Wc1 : (w==1) ? Wc2 : Wc3;
    int KW = (w==0) ? FN : CCH;
    float o[8];
    #pragma unroll
    for (int j = 0; j < 8; j++) {
        int k = grp*8 + j;
        o[pl8(j)] = (k < KW) ? rndtf(W[k*CCH + r]) : 0.f;
    }
    float* dst = g_wr + ((size_t)(w*CCH + r))*AP + grp*8;
    *(float4*)dst       = make_float4(o[0],o[1],o[2],o[3]);
    *(float4*)(dst + 4) = make_float4(o[4],o[5],o[6],o[7]);
}
// x rounded + padded + k interleaved
__global__ void k_xr(const float* __restrict__ x) {
    int i = blockIdx.x*blockDim.x + threadIdx.x;
    if (i >= NNODE*(AP/8)) return;
    int n = i / (AP/8), grp = i % (AP/8);
    float o[8];
    if (grp*8 < FN) {
        #pragma unroll
        for (int j = 0; j < 8; j++) o[pl8(j)] = rndtf(x[(size_t)n*FN + grp*8 + j]);
    } else {
        #pragma unroll
        for (int j = 0; j < 8; j++) o[j] = 0.f;
    }
    float* dst = g_xr + (size_t)n*AP + grp*8;
    *(float4*)dst       = make_float4(o[0],o[1],o[2],o[3]);
    *(float4*)(dst + 4) = make_float4(o[4],o[5],o[6],o[7]);
}
__global__ void k_count_deg(const int* __restrict__ dst) {
    int i = blockIdx.x*blockDim.x + threadIdx.x;
    if (i < NEDGE) atomicAdd(&g_dinv[dst[i]], 1.0f);
}
__global__ void k_make_dinv() {
    int i = blockIdx.x*blockDim.x + threadIdx.x;
    if (i < NNODE) g_dinv[i] = rsqrtf(g_dinv[i] + 1.0f);
}
__global__ void k_build(const int* __restrict__ src, const int* __restrict__ dst) {
    int i = blockIdx.x*blockDim.x + threadIdx.x;
    if (i < NEDGE) {
        int d = dst[i], s = src[i];
        int b = d / FN, r = d - b*FN, c = s - b*FN;
        atomicAdd(&g_A[((size_t)b*AP + r)*AP + c], g_dinv[s]*g_dinv[d]);
    } else if (i < NEDGE + NNODE) {
        int n = i - NEDGE, b = n / FN, r = n - b*FN;
        atomicAdd(&g_A[((size_t)b*AP + r)*AP + r], g_dinv[n]*g_dinv[n]);
    }
}
// round to tf32 AND interleave k within 8-groups (in place, one group per thread)
__global__ void k_round_A() {
    size_t stride = (size_t)gridDim.x*blockDim.x;
    size_t tot = (size_t)BGRAPH*AP*AP/8;
    for (size_t i = blockIdx.x*blockDim.x + threadIdx.x; i < tot; i += stride) {
        float* p = g_A + i*8;
        float4 a = *(float4*)p, b = *(float4*)(p+4);
        float in[8] = {a.x,a.y,a.z,a.w,b.x,b.y,b.z,b.w};
        float o[8];
        #pragma unroll
        for (int j = 0; j < 8; j++) o[pl8(j)] = rndtf(in[j]);
        *(float4*)p     = make_float4(o[0],o[1],o[2],o[3]);
        *(float4*)(p+4) = make_float4(o[4],o[5],o[6],o[7]);
    }
}

// ---------------- tf32 HMMA GEMM, cp.async + v2 fragment loads ----
// 128x128 tile, BK=32, 256 thr (8 warps 2x4, warp 64x32).
// A always k-interleaved [row][k ilv]. B: MODE0/1 n-major interleaved [n][k ilv];
// MODE2 raw row-major [k][n], scalar bf loads.
// MODE 0: XW -> writes h^T[b][c][j ilv], rounded. grid(360)
// MODE 1: AH -> xs[node][c ilv] = rndtf(tanh(D+bias)). grid(3, BGRAPH), y = graph, colBase=0
// MODE 2: split-K atomicAdd into Cg[M x H1]; B rows clamped to KREAL-1.
template<int MODE>
__global__ __launch_bounds__(256)
void gk(const float* __restrict__ Ag, const float* __restrict__ Bg,
        const float* __restrict__ bias, float* __restrict__ Cg,
        int lda, int ldb, int M, int K, int KREAL, int kchunk)
{
    extern __shared__ __align__(16) float dyn[];
    const int tid = threadIdx.x, lane = tid & 31, w = tid >> 5;
    const int wm = (w & 1)*64, wn = (w >> 1)*32;
    const int g = lane >> 2, kt = lane & 3;
    const int rowBase = blockIdx.x*128;
    const int colBase = (MODE == 1) ? 0 : blockIdx.y*128;

    if (MODE == 1) {
        Ag += (size_t)blockIdx.y * AP * AP;
        Bg += (size_t)blockIdx.y * CCH * AP;
    }
    int kbeg = 0, kend = K;
    if (MODE == 2) { kbeg = blockIdx.z*kchunk; kend = min(K, kbeg + kchunk); }

    const int STG = 10240;   // floats/stage: A 128x40 (5120) + B 5120 (128x40 or 32x132+pad)
    const int am = tid >> 1;              // A row (2 threads/row)
    const int ak = (tid & 1) * 16;        // A col block (16 floats)
    const int bk = tid >> 3;              // MODE2 B row 0..31
    const int bn = (tid & 7) * 16;        // MODE2 B col block

    auto load_chunk = [&](int c, int stg) {
        int k0 = kbeg + c*32;
        float* As = dyn + stg*STG;
        float* Bs = As + 5120;
        const float* ar = Ag + (size_t)(rowBase + am)*lda + k0 + ak;
        uint32_t ad = s2u(As + am*40 + ak);
        cpa16(ad,      ar);
        cpa16(ad + 16, ar + 4);
        cpa16(ad + 32, ar + 8);
        cpa16(ad + 48, ar + 12);
        if (MODE == 2) {
            int kg = min(k0 + bk, KREAL - 1);
            const float* br = Bg + (size_t)kg*ldb + colBase + bn;
            uint32_t bd = s2u(Bs + bk*132 + bn);
            cpa16(bd,      br);
            cpa16(bd + 16, br + 4);
            cpa16(bd + 32, br + 8);
            cpa16(bd + 48, br + 12);
        } else {
            const float* br = Bg + (size_t)am*ldb + k0 + ak;   // n-major B
            uint32_t bd = s2u(Bs + am*40 + ak);
            cpa16(bd,      br);
            cpa16(bd + 16, br + 4);
            cpa16(bd + 32, br + 8);
            cpa16(bd + 48, br + 12);
        }
        asm volatile("cp.async.commit_group;" ::: "memory");
    };

    float acc[4][4][4];
    #pragma unroll
    for (int mi = 0; mi < 4; mi++)
        #pragma unroll
        for (int nj = 0; nj < 4; nj++)
            #pragma unroll
            for (int r = 0; r < 4; r++) acc[mi][nj][r] = 0.f;

    const int nch = (kend - kbeg) >> 5;
    load_chunk(0, 0);
    for (int c = 0; c < nch; c++) {
        int buf = c & 1;
        if (c + 1 < nch) {
            load_chunk(c + 1, buf ^ 1);
            asm volatile("cp.async.wait_group 1;" ::: "memory");
        } else {
            asm volatile("cp.async.wait_group 0;" ::: "memory");
        }
        __syncthreads();
        const float* As = dyn + buf*STG;
        const float* Bs = As + 5120;
        #pragma unroll
        for (int ks = 0; ks < 4; ks++) {
            uint32_t af[4][4], bf[4][2];
            #pragma unroll
            for (int mi = 0; mi < 4; mi++) {
                int m = wm + mi*16 + g;
                float2 lo = *(const float2*)&As[(m    )*40 + ks*8 + 2*kt];
                float2 hi = *(const float2*)&As[(m + 8)*40 + ks*8 + 2*kt];
                af[mi][0] = __float_as_uint(lo.x);   // (row m,   kt)
                af[mi][1] = __float_as_uint(hi.x);   // (row m+8, kt)
                af[mi][2] = __float_as_uint(lo.y);   // (row m,   kt+4)
                af[mi][3] = __float_as_uint(hi.y);   // (row m+8, kt+4)
            }
            #pragma unroll
            for (int nj = 0; nj < 4; nj++) {
                int n = wn + nj*8 + g;
                if (MODE == 2) {
                    bf[nj][0] = __float_as_uint(Bs[(ks*8 + kt    )*132 + n]);
                    bf[nj][1] = __float_as_uint(Bs[(ks*8 + kt + 4)*132 + n]);
                } else {
                    float2 v = *(const float2*)&Bs[n*40 + ks*8 + 2*kt];
                    bf[nj][0] = __float_as_uint(v.x);
                    bf[nj][1] = __float_as_uint(v.y);
                }
            }
            #pragma unroll
            for (int mi = 0; mi < 4; mi++)
                #pragma unroll
                for (int nj = 0; nj < 4; nj++)
                    mma8(acc[mi][nj], af[mi], bf[nj]);
        }
        __syncthreads();
    }

    #pragma unroll
    for (int mi = 0; mi < 4; mi++)
        #pragma unroll
        for (int nj = 0; nj < 4; nj++)
            #pragma unroll
            for (int r = 0; r < 4; r++) {
                int gm = rowBase + wm + mi*16 + g + (r>>1)*8;
                int gn = colBase + wn + nj*8 + kt*2 + (r&1);
                float v = acc[mi][nj][r];
                if (MODE == 0) {
                    int b = gm / FN, j = gm - b*FN;
                    g_h[((size_t)b*CCH + gn)*AP + ilv8(j)] = rndtf(v);   // h^T, j ilv
                } else if (MODE == 1) {
                    if (gm < M) {
                        float* dst = Cg + ((size_t)blockIdx.y*FN + gm)*CCH;
                        dst[ilv8(gn)] = rndtf(fast_tanh(v + __ldg(bias + gn)));
                    }
                } else {
                    atomicAdd(&Cg[(size_t)gm*H1 + gn], v);
                }
            }
}

// ---------------- legacy tf32 mma.sync GEMM (small MLP layers) ----------------
__global__ __launch_bounds__(256)
void mmak(const float* __restrict__ A, const float* __restrict__ Bm,
          float* __restrict__ C, int M, int N, int K)
{
    __shared__ uint32_t As[2][16][PADK];
    __shared__ uint32_t Bs[2][16][PADK];
    const int tid = threadIdx.x, lane = tid & 31, w = tid >> 5;
    const int wm = (w & 1)*64, wn = (w >> 1)*32;
    const int g = lane >> 2, kt = lane & 3;
    const int rowBase = blockIdx.x*128, colBase = blockIdx.y*128;
    const int aRow = tid >> 1, aCol = (tid & 1)*8;
    const int bRow = tid >> 4, bCol = (tid & 15)*8;
    float acc[4][4][4];
    #pragma unroll
    for (int mi = 0; mi < 4; mi++)
        #pragma unroll
        for (int nj = 0; nj < 4; nj++)
            #pragma unroll
            for (int r = 0; r < 4; r++) acc[mi][nj][r] = 0.f;
    const int gmA = rowBase + aRow;
    float4 pa[2], pb[2];
    auto loadT = [&](int k0) {
        #pragma unroll
        for (int h = 0; h < 2; h++) {
            int gk = k0 + aCol + h*4;
            float4 v = make_float4(0.f,0.f,0.f,0.f);
            if (gmA < M && gk + 3 < K) v = *(const float4*)(A + (size_t)gmA*K + gk);
            pa[h] = v;
        }
        int gk = k0 + bRow;
        #pragma unroll
        for (int h = 0; h < 2; h++) {
            int gn = colBase + bCol + h*4;
            float4 v = make_float4(0.f,0.f,0.f,0.f);
            if (gk < K && gn < N) v = *(const float4*)(Bm + (size_t)gk*N + gn);
            pb[h] = v;
        }
    };
    auto storeT = [&](int buf) {
        #pragma unroll
        for (int h = 0; h < 2; h++) {
            As[buf][aCol+h*4+0][aRow] = f2tf(pa[h].x);
            As[buf][aCol+h*4+1][aRow] = f2tf(pa[h].y);
            As[buf][aCol+h*4+2][aRow] = f2tf(pa[h].z);
            As[buf][aCol+h*4+3][aRow] = f2tf(pa[h].w);
            Bs[buf][bRow][bCol+h*4+0] = f2tf(pb[h].x);
            Bs[buf][bRow][bCol+h*4+1] = f2tf(pb[h].y);
            Bs[buf][bRow][bCol+h*4+2] = f2tf(pb[h].z);
            Bs[buf][bRow][bCol+h*4+3] = f2tf(pb[h].w);
        }
    };
    auto comp = [&](int buf) {
        #pragma unroll
        for (int ks = 0; ks < 2; ks++) {
            uint32_t af[4][4], bf[4][2];
            #pragma unroll
            for (int mi = 0; mi < 4; mi++) {
                int m = wm + mi*16;
                af[mi][0] = As[buf][ks*8+kt  ][m+g  ];
                af[mi][1] = As[buf][ks*8+kt  ][m+g+8];
                af[mi][2] = As[buf][ks*8+kt+4][m+g  ];
                af[mi][3] = As[buf][ks*8+kt+4][m+g+8];
            }
            #pragma unroll
            for (int nj = 0; nj < 4; nj++) {
                int n = wn + nj*8;
                bf[nj][0] = Bs[buf][ks*8+kt  ][n+g];
                bf[nj][1] = Bs[buf][ks*8+kt+4][n+g];
            }
            #pragma unroll
            for (int mi = 0; mi < 4; mi++)
                #pragma unroll
                for (int nj = 0; nj < 4; nj++) mma8(acc[mi][nj], af[mi], bf[nj]);
        }
    };
    const int nIter = (K + 15) >> 4;
    loadT(0); storeT(0); __syncthreads();
    for (int t = 1; t < nIter; t++) {
        loadT(t*16);
        comp((t-1) & 1);
        storeT(t & 1);
        __syncthreads();
    }
    comp((nIter-1) & 1);
    #pragma unroll
    for (int mi = 0; mi < 4; mi++)
        #pragma unroll
        for (int nj = 0; nj < 4; nj++)
            #pragma unroll
            for (int r = 0; r < 4; r++) {
                int gm = rowBase + wm + mi*16 + g + (r>>1)*8;
                int gn = colBase + wn + nj*8 + kt*2 + (r&1);
                if (gm < M && gn < N) C[(size_t)gm*N + gn] = acc[mi][nj][r];
            }
}

// ---------------- BN / pool / head ----------------
__global__ void k_x0_bn(const float* __restrict__ x, const float* __restrict__ g,
                        const float* __restrict__ be, float* __restrict__ z)
{
    int r = blockIdx.x;
    int c = r + threadIdx.x;
    if (c >= FN) return;
    long j = (long)r*FN - (long)r*(r-1)/2 + (c - r);
    long zi = (j & ~7L) + 2*(j & 3) + ((j >> 2) & 1);   // interleaved z col
    float s = 0.f, ss = 0.f;
    for (int b = 0; b < BGRAPH; b++) {
        float v = x[((size_t)(b*FN + r))*FN + c];
        s += v; ss += v*v;
    }
    float m = s*(1.f/BGRAPH);
    float var = ss*(1.f/BGRAPH) - m*m;
    float sc = rsqrtf(var + EPSV)*g[j];
    float bb = be[j];
    for (int b = 0; b < BGRAPH; b++) {
        float v = x[((size_t)(b*FN + r))*FN + c];
        z[(size_t)b*ZP + zi] = rndtf((v - m)*sc + bb);
    }
}
// xs has interleaved channels: position k holds original channel orig8(k)
__global__ void k_pool(const float* __restrict__ x1, const float* __restrict__ x2,
                       const float* __restrict__ x3, float* __restrict__ hp)
{
    int b = blockIdx.x, l = blockIdx.y, k = threadIdx.x;
    const float* base = (l==0 ? x1 : l==1 ? x2 : x3) + (size_t)b*FN*CCH + k;
    float s0=0.f, s1=0.f, s2=0.f, s3=0.f;
    #pragma unroll 1
    for (int n = 0; n < FN; n += 4) {
        s0 += base[(size_t)(n+0)*CCH];
        s1 += base[(size_t)(n+1)*CCH];
        s2 += base[(size_t)(n+2)*CCH];
        s3 += base[(size_t)(n+3)*CCH];
    }
    int oc = (k & ~7) + ((k & 1) << 2) + ((k >> 1) & 3);   // original channel
    hp[b*384 + l*CCH + oc] = (s0+s1+s2+s3)*(1.0f/FN);
}
__global__ void k_bn_pool(const float* __restrict__ hp, const float* __restrict__ g,
                          const float* __restrict__ be, float* __restrict__ z)
{
    int j = blockIdx.x*blockDim.x + threadIdx.x;
    if (j >= 396) return;
    long cg2 = (long)TRI + j;
    long zi = (cg2 & ~7L) + 2*(cg2 & 3) + ((cg2 >> 2) & 1);
    if (j >= 384) {
        for (int b = 0; b < BGRAPH; b++) z[(size_t)b*ZP + zi] = 0.f;
        return;
    }
    float s = 0.f, ss = 0.f;
    for (int b = 0; b < BGRAPH; b++) { float v = hp[b*384 + j]; s += v; ss += v*v; }
    float m = s*(1.f/BGRAPH);
    float var = ss*(1.f/BGRAPH) - m*m;
    float sc = rsqrtf(var + EPSV)*g[j];
    float bb = be[j];
    for (int b = 0; b < BGRAPH; b++)
        z[(size_t)b*ZP + zi] = rndtf((hp[b*384 + j] - m)*sc + bb);
}
__global__ void k_bn_relu(const float* __restrict__ X, const float* __restrict__ bias,
                          const float* __restrict__ gam, const float* __restrict__ bet,
                          float* __restrict__ Y, int ncols)
{
    int col = blockIdx.x, t = threadIdx.x;
    float v = X[t*ncols + col] + bias[col];
    float s = v, ss = v*v;
    #pragma unroll
    for (int o = 16; o > 0; o >>= 1) {
        s  += __shfl_down_sync(0xffffffffu, s,  o);
        ss += __shfl_down_sync(0xffffffffu, ss, o);
    }
    __shared__ float ws[4], wss[4];
    __shared__ float sm, sscale;
    int wid = t >> 5, lane = t & 31;
    if (lane == 0) { ws[wid] = s; wss[wid] = ss; }
    __syncthreads();
    if (t == 0) {
        float S = ws[0]+ws[1]+ws[2]+ws[3];
        float SS = wss[0]+wss[1]+wss[2]+wss[3];
        float m = S*(1.f/BGRAPH);
        sm = m; sscale = rsqrtf(SS*(1.f/BGRAPH) - m*m + EPSV);
    }
    __syncthreads();
    float o = (v - sm)*sscale*gam[col] + bet[col];
    Y[t*ncols + col] = fmaxf(o, 0.f);
}
__global__ void k_head(const float* __restrict__ a3, const float* __restrict__ W4,
                       const float* __restrict__ b4, float* __restrict__ out)
{
    int b = blockIdx.x, lane = threadIdx.x;
    float s0 = 0.f, s1 = 0.f;
    for (int i = lane; i < H2; i += 32) {
        float v = a3[b*H2 + i];
        s0 = fmaf(v, W4[i*2+0], s0);
        s1 = fmaf(v, W4[i*2+1], s1);
    }
    #pragma unroll
    for (int o = 16; o > 0; o >>= 1) {
        s0 += __shfl_down_sync(0xffffffffu, s0, o);
        s1 += __shfl_down_sync(0xffffffffu, s1, o);
    }
    if (lane == 0) {
        float l0 = s0 + b4[0], l1 = s1 + b4[1];
        float m = fmaxf(l0, l1);
        float lse = m + logf(expf(l0-m) + expf(l1-m));
        out[b*2+0] = l0 - lse;
        out[b*2+1] = l1 - lse;
    }
}

// ---------------- launch ----------------
extern "C" void kernel_launch(void* const* d_in, const int* in_sizes, int n_in,
                              void* d_out, int out_size)
{
    const float* x    = (const float*)d_in[0];
    const int*   esrc = (const int*)d_in[1];
    const int*   edst = (const int*)d_in[2];
    const float* Wc1  = (const float*)d_in[4];
    const float* bc1  = (const float*)d_in[5];
    const float* Wc2  = (const float*)d_in[6];
    const float* bc2  = (const float*)d_in[7];
    const float* Wc3  = (const float*)d_in[8];
    const float* bc3  = (const float*)d_in[9];
    const float* bn_g = (const float*)d_in[10];
    const float* bn_b = (const float*)d_in[11];
    const float* bnh_g= (const float*)d_in[12];
    const float* bnh_b= (const float*)d_in[13];
    const float* W1   = (const float*)d_in[14];
    const float* b1   = (const float*)d_in[15];
    const float* g1   = (const float*)d_in[16];
    const float* be1  = (const float*)d_in[17];
    const float* W2   = (const float*)d_in[18];
    const float* b2   = (const float*)d_in[19];
    const float* g2   = (const float*)d_in[20];
    const float* be2  = (const float*)d_in[21];
    const float* W3   = (const float*)d_in[22];
    const float* b3   = (const float*)d_in[23];
    const float* g3   = (const float*)d_in[24];
    const float* be3  = (const float*)d_in[25];
    const float* W4   = (const float*)d_in[26];
    const float* b4   = (const float*)d_in[27];
    float* out = (float*)d_out;

    const int DSM = 2*10240*4;   // 81920 bytes
    cudaFuncSetAttribute(gk<0>, cudaFuncAttributeMaxDynamicSharedMemorySize, DSM);
    cudaFuncSetAttribute(gk<1>, cudaFuncAttributeMaxDynamicSharedMemorySize, DSM);
    cudaFuncSetAttribute(gk<2>, cudaFuncAttributeMaxDynamicSharedMemorySize, DSM);

    void *pDinv, *pA, *pXr, *pWr, *pH, *pX1, *pX2, *pX3, *pZ, *pHp, *pA1, *pA2, *pA3;
    cudaGetSymbolAddress(&pDinv, g_dinv);
    cudaGetSymbolAddress(&pA,  g_A);
    cudaGetSymbolAddress(&pXr, g_xr);
    cudaGetSymbolAddress(&pWr, g_wr);
    cudaGetSymbolAddress(&pH,  g_h);
    cudaGetSymbolAddress(&pX1, g_xs1);
    cudaGetSymbolAddress(&pX2, g_xs2);
    cudaGetSymbolAddress(&pX3, g_xs3);
    cudaGetSymbolAddress(&pZ,  g_z);
    cudaGetSymbolAddress(&pHp, g_hpool);
    cudaGetSymbolAddress(&pA1, g_a1);
    cudaGetSymbolAddress(&pA2, g_a2);
    cudaGetSymbolAddress(&pA3, g_a3);

    const float* xr = (const float*)pXr;
    const float* wr = (const float*)pWr;
    const float* hT = (const float*)pH;

    // order chosen so launch index 5 (ncu -s 5) is the first big GEMM (XW1)
    cudaMemsetAsync(pH, 0, (size_t)BGRAPH*CCH*AP*4, 0);            // 0
    cudaMemsetAsync(pDinv, 0, (size_t)NNODE*4, 0);                 // 1
    cudaMemsetAsync(pA, 0, (size_t)BGRAPH*AP*AP*4, 0);             // 2
    k_prep<<<(3*CCH*(AP/8)+255)/256, 256>>>(Wc1, Wc2, Wc3);        // 3
    k_xr<<<(NNODE*(AP/8)+255)/256, 256>>>(x);                      // 4
    gk<0><<<dim3(360,1), 256, DSM>>>(xr, wr, nullptr, nullptr,     // 5  <- ncu target
                                     AP, AP, NNODE, AP, AP, 0);
    k_count_deg<<<(NEDGE+255)/256, 256>>>(edst);                   // 6
    k_make_dinv<<<(NNODE+255)/256, 256>>>();                       // 7
    k_build<<<(NEDGE+NNODE+255)/256, 256>>>(esrc, edst);           // 8
    k_round_A<<<2048, 256>>>();                                    // 9

    gk<1><<<dim3(3,BGRAPH), 256, DSM>>>((const float*)pA, hT, bc1, (float*)pX1,
                                        AP, AP, FN, AP, AP, 0);
    gk<0><<<dim3(360,1), 256, DSM>>>((const float*)pX1, wr + (size_t)CCH*AP, nullptr, nullptr,
                                     CCH, AP, NNODE, CCH, CCH, 0);
    gk<1><<<dim3(3,BGRAPH), 256, DSM>>>((const float*)pA, hT, bc2, (float*)pX2,
                                        AP, AP, FN, AP, AP, 0);
    gk<0><<<dim3(360,1), 256, DSM>>>((const float*)pX2, wr + (size_t)2*CCH*AP, nullptr, nullptr,
                                     CCH, AP, NNODE, CCH, CCH, 0);
    gk<1><<<dim3(3,BGRAPH), 256, DSM>>>((const float*)pA, hT, bc3, (float*)pX3,
                                        AP, AP, FN, AP, AP, 0);

    // features
    k_x0_bn<<<FN, 384>>>(x, bn_g, bn_b, (float*)pZ);
    k_pool<<<dim3(BGRAPH,3), CCH>>>((const float*)pX1, (const float*)pX2, (const float*)pX3, (float*)pHp);
    k_bn_pool<<<1, 512>>>((const float*)pHp, bnh_g, bnh_b, (float*)pZ);

    // MLP
    cudaMemsetAsync(pA1, 0, (size_t)BGRAPH*H1*4, 0);
    gk<2><<<dim3(1,4,64), 256, DSM>>>((const float*)pZ, W1, nullptr, (float*)pA1,
                                      ZP, H1, BGRAPH, ZP, D1, 1024);
    k_bn_relu<<<H1, 128>>>((const float*)pA1, b1, g1, be1, (float*)pA1, H1);
    mmak<<<dim3(1,2), 256>>>((const float*)pA1, W2, (float*)pA2, BGRAPH, H2, H1);
    k_bn_relu<<<H2, 128>>>((const float*)pA2, b2, g2, be2, (float*)pA2, H2);
    mmak<<<dim3(1,2), 256>>>((const float*)pA2, W3, (float*)pA3, BGRAPH, H2, H2);
    k_bn_relu<<<H2, 128>>>((const float*)pA3, b3, g3, be3, (float*)pA3, H2);
    k_head<<<BGRAPH, 32>>>((const float*)pA3, W4, b4, out);
}

// round 10
// speedup vs baseline: 1.2164x; 1.2164x over previous
#include <cuda_runtime.h>
#include <cuda_fp16.h>
#include <math.h>
#include <stdint.h>

#define FN 360
#define BGRAPH 128
#define NNODE (FN*BGRAPH)
#define NEDGE 1000000
#define CCH 128
#define TRI 64980
#define D1 65364
#define ZP 65376
#define H1 512
#define H2 256
#define EPSV 1e-5f
#define PADK 136
#define AP 384

// ---------------- scratch ----------------
__device__ __align__(16) float  g_dinv[NNODE];
__device__ __align__(16) float  g_A [(size_t)BGRAPH*AP*AP];   // fp32 atomic build
__device__ __align__(16) __half g_Ah[(size_t)BGRAPH*AP*AP];   // fp16, ilv16 k
__device__ __align__(16) __half g_xh[(size_t)NNODE*AP];       // fp16 x, ilv16 k
__device__ __align__(16) __half g_wh[(size_t)3*CCH*AP];       // fp16 W^T, ilv16 k
__device__ __align__(16) __half g_hh[(size_t)BGRAPH*CCH*AP];  // fp16 h^T [b][c][j ilv16]
__device__ __align__(16) __half g_x1h[(size_t)NNODE*CCH];     // fp16 xs, ilv16 ch
__device__ __align__(16) __half g_x2h[(size_t)NNODE*CCH];
__device__ __align__(16) __half g_x3h[(size_t)NNODE*CCH];
__device__ __align__(16) float  g_z[(size_t)BGRAPH*ZP];       // fp32, ilv8 cols
__device__ __align__(16) float  g_hpool[BGRAPH*384];
__device__ __align__(16) float  g_a1[BGRAPH*H1];
__device__ __align__(16) float  g_a2[BGRAPH*H2];
__device__ __align__(16) float  g_a3[BGRAPH*H2];

// ---------------- helpers ----------------
__device__ __forceinline__ uint32_t f2tf(float f) {
    uint32_t u; asm("cvt.rna.tf32.f32 %0, %1;" : "=r"(u) : "f"(f)); return u;
}
__device__ __forceinline__ float rndtf(float f) { return __uint_as_float(f2tf(f)); }
// fp16 path: interleave within 16-groups so halfs at pos 4kt..4kt+3 are k = {2kt,2kt+1,2kt+8,2kt+9}
__device__ __forceinline__ int pl16(int j)  { int p=j>>1, b=j&1; return ((p&3)<<2)|(((p>>2)&1)<<1)|b; }
__device__ __forceinline__ int ilv16(int c) { return (c & ~15) + pl16(c & 15); }
__device__ __forceinline__ int orig16p(int q){ int b=q&1, t=(q>>1)&7; int p=((t&1)<<2)|(t>>1); return 2*p+b; }
__device__ __forceinline__ float fast_tanh(float x) {
    float e = __expf(2.0f*x);
    return 1.0f - __fdividef(2.0f, e + 1.0f);
}
__device__ __forceinline__ uint32_t s2u(const void* p) {
    uint32_t a;
    asm("{ .reg .u64 t; cvta.to.shared.u64 t, %1; cvt.u32.u64 %0, t; }" : "=r"(a) : "l"(p));
    return a;
}
__device__ __forceinline__ void cpa16(uint32_t d, const void* g) {
    asm volatile("cp.async.cg.shared.global [%0], [%1], 16;" :: "r"(d), "l"(g));
}
__device__ __forceinline__ void mma8(float* c, const uint32_t* a, const uint32_t* b) {
    asm volatile("mma.sync.aligned.m16n8k8.row.col.f32.tf32.tf32.f32 "
        "{%0,%1,%2,%3}, {%4,%5,%6,%7}, {%8,%9}, {%0,%1,%2,%3};"
        : "+f"(c[0]), "+f"(c[1]), "+f"(c[2]), "+f"(c[3])
        : "r"(a[0]), "r"(a[1]), "r"(a[2]), "r"(a[3]), "r"(b[0]), "r"(b[1]));
}
__device__ __forceinline__ void mma16(float* c, const uint32_t* a, const uint32_t* b) {
    asm volatile("mma.sync.aligned.m16n8k16.row.col.f32.f16.f16.f32 "
        "{%0,%1,%2,%3}, {%4,%5,%6,%7}, {%8,%9}, {%0,%1,%2,%3};"
        : "+f"(c[0]), "+f"(c[1]), "+f"(c[2]), "+f"(c[3])
        : "r"(a[0]), "r"(a[1]), "r"(a[2]), "r"(a[3]), "r"(b[0]), "r"(b[1]));
}

// ---------------- prep ----------------
__global__ void k_prep(const float* __restrict__ Wc1, const float* __restrict__ Wc2,
                       const float* __restrict__ Wc3) {
    int i = blockIdx.x*blockDim.x + threadIdx.x;
    if (i >= 3*CCH*(AP/16)) return;
    int w = i / (CCH*(AP/16));
    int r = (i / (AP/16)) % CCH;
    int grp = i % (AP/16);
    const float* W = (w==0) ? Wc1 : (w==1) ? Wc2 : Wc3;
    int KW = (w==0) ? FN : CCH;
    __align__(16) __half o[16];
    #pragma unroll
    for (int j = 0; j < 16; j++) {
        int k = grp*16 + j;
        o[pl16(j)] = (k < KW) ? __float2half_rn(W[k*CCH + r]) : __half(0.f);
    }
    __half* dst = g_wh + ((size_t)(w*CCH + r))*AP + grp*16;
    ((uint4*)dst)[0] = ((uint4*)o)[0];
    ((uint4*)dst)[1] = ((uint4*)o)[1];
}
__global__ void k_xh(const float* __restrict__ x) {
    int i = blockIdx.x*blockDim.x + threadIdx.x;
    if (i >= NNODE*(AP/16)) return;
    int n = i / (AP/16), grp = i % (AP/16);
    __align__(16) __half o[16];
    #pragma unroll
    for (int j = 0; j < 16; j++) {
        int k = grp*16 + j;
        o[pl16(j)] = (k < FN) ? __float2half_rn(x[(size_t)n*FN + k]) : __half(0.f);
    }
    __half* dst = g_xh + (size_t)n*AP + grp*16;
    ((uint4*)dst)[0] = ((uint4*)o)[0];
    ((uint4*)dst)[1] = ((uint4*)o)[1];
}
__global__ void k_count_deg(const int* __restrict__ dst) {
    int i = blockIdx.x*blockDim.x + threadIdx.x;
    if (i < NEDGE) atomicAdd(&g_dinv[dst[i]], 1.0f);
}
__global__ void k_make_dinv() {
    int i = blockIdx.x*blockDim.x + threadIdx.x;
    if (i < NNODE) g_dinv[i] = rsqrtf(g_dinv[i] + 1.0f);
}
__global__ void k_build(const int* __restrict__ src, const int* __restrict__ dst) {
    int i = blockIdx.x*blockDim.x + threadIdx.x;
    if (i < NEDGE) {
        int d = dst[i], s = src[i];
        int b = d / FN, r = d - b*FN, c = s - b*FN;
        atomicAdd(&g_A[((size_t)b*AP + r)*AP + c], g_dinv[s]*g_dinv[d]);
    } else if (i < NEDGE + NNODE) {
        int n = i - NEDGE, b = n / FN, r = n - b*FN;
        atomicAdd(&g_A[((size_t)b*AP + r)*AP + r], g_dinv[n]*g_dinv[n]);
    }
}
// fp32 A -> fp16 A, k interleaved per 16 (conversion IS the rounding)
__global__ void k_convA() {
    size_t stride = (size_t)gridDim.x*blockDim.x;
    size_t tot = (size_t)BGRAPH*AP*AP/16;
    for (size_t i = blockIdx.x*blockDim.x + threadIdx.x; i < tot; i += stride) {
        const float* p = g_A + i*16;
        float in[16];
        #pragma unroll
        for (int q = 0; q < 4; q++) {
            float4 v = ((const float4*)p)[q];
            in[q*4+0]=v.x; in[q*4+1]=v.y; in[q*4+2]=v.z; in[q*4+3]=v.w;
        }
        __align__(16) __half o[16];
        #pragma unroll
        for (int j = 0; j < 16; j++) o[pl16(j)] = __float2half_rn(in[j]);
        __half* dst = g_Ah + i*16;
        ((uint4*)dst)[0] = ((uint4*)o)[0];
        ((uint4*)dst)[1] = ((uint4*)o)[1];
    }
}

// ---------------- fp16 HMMA GEMM (GCN path), 3-stage cp.async ----------------
// 128x128 tile, BK=32, 256 thr (8 warps 2x4, warp 64x32). A [m][k ilv16], B [n][k ilv16].
// MODE 0: XW -> g_hh[(b*CCH+c)*AP + ilv16(j)]. grid(360)
// MODE 1: AH -> xs fp16 [node][ilv16(c)] = tanh(D+bias). grid(3, BGRAPH), y = graph
template<int MODE>
__global__ __launch_bounds__(256)
void gkh(const __half* __restrict__ Ag, const __half* __restrict__ Bg,
         const float* __restrict__ bias, __half* __restrict__ Cg,
         int lda, int ldb, int M, int K)
{
    extern __shared__ __align__(16) __half dynh[];
    const int STG = 12288;                 // halfs/stage: A 128x48 + B 128x48
    const int tid = threadIdx.x, lane = tid & 31, w = tid >> 5;
    const int wm = (w & 1)*64, wn = (w >> 1)*32;
    const int g = lane >> 2, kt = lane & 3;
    const int rowBase = blockIdx.x*128;

    if (MODE == 1) {
        Ag += (size_t)blockIdx.y * AP * AP;
        Bg += (size_t)blockIdx.y * CCH * AP;
    }
    const int am = tid >> 1;               // row (A and B), 2 threads/row
    const int ak = (tid & 1) * 16;         // 16-half block within 32-half row

    auto load_chunk = [&](int c, int stg) {
        int k0 = c*32;
        __half* As = dynh + stg*STG;
        __half* Bs = As + 6144;
        const __half* ar = Ag + (size_t)(rowBase + am)*lda + k0 + ak;
        uint32_t ad = s2u(As + am*48 + ak);
        cpa16(ad,      ar);
        cpa16(ad + 16, ar + 8);
        const __half* br = Bg + (size_t)am*ldb + k0 + ak;
        uint32_t bd = s2u(Bs + am*48 + ak);
        cpa16(bd,      br);
        cpa16(bd + 16, br + 8);
        asm volatile("cp.async.commit_group;" ::: "memory");
    };

    float acc[4][4][4];
    #pragma unroll
    for (int mi = 0; mi < 4; mi++)
        #pragma unroll
        for (int nj = 0; nj < 4; nj++)
            #pragma unroll
            for (int r = 0; r < 4; r++) acc[mi][nj][r] = 0.f;

    const int nch = K >> 5;
    load_chunk(0, 0);
    load_chunk(1, 1);
    for (int c = 0; c < nch; c++) {
        int buf = c % 3;
        if (c + 2 < nch) {
            load_chunk(c + 2, (c + 2) % 3);
            asm volatile("cp.async.wait_group 2;" ::: "memory");
        } else if (c + 1 < nch) {
            asm volatile("cp.async.wait_group 1;" ::: "memory");
        } else {
            asm volatile("cp.async.wait_group 0;" ::: "memory");
        }
        __syncthreads();
        const __half* As = dynh + buf*STG;
        const __half* Bs = As + 6144;
        #pragma unroll
        for (int ks = 0; ks < 2; ks++) {
            uint32_t af[4][4], bf[4][2];
            #pragma unroll
            for (int mi = 0; mi < 4; mi++) {
                int m = wm + mi*16 + g;
                uint2 va = *(const uint2*)&As[m*48     + ks*16 + 4*kt];
                uint2 vb = *(const uint2*)&As[(m+8)*48 + ks*16 + 4*kt];
                af[mi][0] = va.x;   // (row m,   k 2kt,2kt+1)
                af[mi][1] = vb.x;   // (row m+8, k 2kt,2kt+1)
                af[mi][2] = va.y;   // (row m,   k 2kt+8,2kt+9)
                af[mi][3] = vb.y;
            }
            #pragma unroll
            for (int nj = 0; nj < 4; nj++) {
                int n = wn + nj*8 + g;
                uint2 u = *(const uint2*)&Bs[n*48 + ks*16 + 4*kt];
                bf[nj][0] = u.x;
                bf[nj][1] = u.y;
            }
            #pragma unroll
            for (int mi = 0; mi < 4; mi++)
                #pragma unroll
                for (int nj = 0; nj < 4; nj++)
                    mma16(acc[mi][nj], af[mi], bf[nj]);
        }
        __syncthreads();
    }

    #pragma unroll
    for (int mi = 0; mi < 4; mi++)
        #pragma unroll
        for (int nj = 0; nj < 4; nj++)
            #pragma unroll
            for (int r = 0; r < 4; r++) {
                int gm = rowBase + wm + mi*16 + g + (r>>1)*8;
                int gn = wn + nj*8 + kt*2 + (r&1);
                float v = acc[mi][nj][r];
                if (MODE == 0) {
                    int b = gm / FN, j = gm - b*FN;
                    g_hh[((size_t)b*CCH + gn)*AP + ilv16(j)] = __float2half_rn(v);
                } else {
                    if (gm < M) {
                        __half* dst = Cg + ((size_t)blockIdx.y*FN + gm)*CCH;
                        dst[ilv16(gn)] = __float2half_rn(fast_tanh(v + __ldg(bias + gn)));
                    }
                }
            }
}

// ---------------- tf32 zW1 GEMM (split-K, unchanged from passing R9 MODE2) ----
__global__ __launch_bounds__(256)
void gkz(const float* __restrict__ Ag, const float* __restrict__ Bg,
         float* __restrict__ Cg, int lda, int ldb, int K, int KREAL, int kchunk)
{
    extern __shared__ __align__(16) float dynf[];
    const int tid = threadIdx.x, lane = tid & 31, w = tid >> 5;
    const int wm = (w & 1)*64, wn = (w >> 1)*32;
    const int g = lane >> 2, kt = lane & 3;
    const int rowBase = blockIdx.x*128;
    const int colBase = blockIdx.y*128;
    int kbeg = blockIdx.z*kchunk, kend = min(K, kbeg + kchunk);

    const int STG = 10240;
    const int am = tid >> 1;
    const int ak = (tid & 1) * 16;
    const int bk = tid >> 3;
    const int bn = (tid & 7) * 16;

    auto load_chunk = [&](int c, int stg) {
        int k0 = kbeg + c*32;
        float* As = dynf + stg*STG;
        float* Bs = As + 5120;
        const float* ar = Ag + (size_t)(rowBase + am)*lda + k0 + ak;
        uint32_t ad = s2u(As + am*40 + ak);
        cpa16(ad,      ar);
        cpa16(ad + 16, ar + 4);
        cpa16(ad + 32, ar + 8);
        cpa16(ad + 48, ar + 12);
        int kg = min(k0 + bk, KREAL - 1);
        const float* br = Bg + (size_t)kg*ldb + colBase + bn;
        uint32_t bd = s2u(Bs + bk*132 + bn);
        cpa16(bd,      br);
        cpa16(bd + 16, br + 4);
        cpa16(bd + 32, br + 8);
        cpa16(bd + 48, br + 12);
        asm volatile("cp.async.commit_group;" ::: "memory");
    };

    float acc[4][4][4];
    #pragma unroll
    for (int mi = 0; mi < 4; mi++)
        #pragma unroll
        for (int nj = 0; nj < 4; nj++)
            #pragma unroll
            for (int r = 0; r < 4; r++) acc[mi][nj][r] = 0.f;

    const int nch = (kend - kbeg) >> 5;
    load_chunk(0, 0);
    for (int c = 0; c < nch; c++) {
        int buf = c & 1;
        if (c + 1 < nch) {
            load_chunk(c + 1, buf ^ 1);
            asm volatile("cp.async.wait_group 1;" ::: "memory");
        } else {
            asm volatile("cp.async.wait_group 0;" ::: "memory");
        }
        __syncthreads();
        const float* As = dynf + buf*STG;
        const float* Bs = As + 5120;
        #pragma unroll
        for (int ks = 0; ks < 4; ks++) {
            uint32_t af[4][4], bf[4][2];
            #pragma unroll
            for (int mi = 0; mi < 4; mi++) {
                int m = wm + mi*16 + g;
                float2 lo = *(const float2*)&As[(m    )*40 + ks*8 + 2*kt];
                float2 hi = *(const float2*)&As[(m + 8)*40 + ks*8 + 2*kt];
                af[mi][0] = __float_as_uint(lo.x);
                af[mi][1] = __float_as_uint(hi.x);
                af[mi][2] = __float_as_uint(lo.y);
                af[mi][3] = __float_as_uint(hi.y);
            }
            #pragma unroll
            for (int nj = 0; nj < 4; nj++) {
                int n = wn + nj*8 + g;
                bf[nj][0] = __float_as_uint(Bs[(ks*8 + kt    )*132 + n]);
                bf[nj][1] = __float_as_uint(Bs[(ks*8 + kt + 4)*132 + n]);
            }
            #pragma unroll
            for (int mi = 0; mi < 4; mi++)
                #pragma unroll
                for (int nj = 0; nj < 4; nj++)
                    mma8(acc[mi][nj], af[mi], bf[nj]);
        }
        __syncthreads();
    }

    #pragma unroll
    for (int mi = 0; mi < 4; mi++)
        #pragma unroll
        for (int nj = 0; nj < 4; nj++)
            #pragma unroll
            for (int r = 0; r < 4; r++) {
                int gm = rowBase + wm + mi*16 + g + (r>>1)*8;
                int gn = colBase + wn + nj*8 + kt*2 + (r&1);
                atomicAdd(&Cg[(size_t)gm*H1 + gn], acc[mi][nj][r]);
            }
}

// ---------------- legacy tf32 mma.sync GEMM (small MLP layers) ----------------
__global__ __launch_bounds__(256)
void mmak(const float* __restrict__ A, const float* __restrict__ Bm,
          float* __restrict__ C, int M, int N, int K)
{
    __shared__ uint32_t As[2][16][PADK];
    __shared__ uint32_t Bs[2][16][PADK];
    const int tid = threadIdx.x, lane = tid & 31, w = tid >> 5;
    const int wm = (w & 1)*64, wn = (w >> 1)*32;
    const int g = lane >> 2, kt = lane & 3;
    const int rowBase = blockIdx.x*128, colBase = blockIdx.y*128;
    const int aRow = tid >> 1, aCol = (tid & 1)*8;
    const int bRow = tid >> 4, bCol = (tid & 15)*8;
    float acc[4][4][4];
    #pragma unroll
    for (int mi = 0; mi < 4; mi++)
        #pragma unroll
        for (int nj = 0; nj < 4; nj++)
            #pragma unroll
            for (int r = 0; r < 4; r++) acc[mi][nj][r] = 0.f;
    const int gmA = rowBase + aRow;
    float4 pa[2], pb[2];
    auto loadT = [&](int k0) {
        #pragma unroll
        for (int h = 0; h < 2; h++) {
            int gk = k0 + aCol + h*4;
            float4 v = make_float4(0.f,0.f,0.f,0.f);
            if (gmA < M && gk + 3 < K) v = *(const float4*)(A + (size_t)gmA*K + gk);
            pa[h] = v;
        }
        int gk = k0 + bRow;
        #pragma unroll
        for (int h = 0; h < 2; h++) {
            int gn = colBase + bCol + h*4;
            float4 v = make_float4(0.f,0.f,0.f,0.f);
            if (gk < K && gn < N) v = *(const float4*)(Bm + (size_t)gk*N + gn);
            pb[h] = v;
        }
    };
    auto storeT = [&](int buf) {
        #pragma unroll
        for (int h = 0; h < 2; h++) {
            As[buf][aCol+h*4+0][aRow] = f2tf(pa[h].x);
            As[buf][aCol+h*4+1][aRow] = f2tf(pa[h].y);
            As[buf][aCol+h*4+2][aRow] = f2tf(pa[h].z);
            As[buf][aCol+h*4+3][aRow] = f2tf(pa[h].w);
            Bs[buf][bRow][bCol+h*4+0] = f2tf(pb[h].x);
            Bs[buf][bRow][bCol+h*4+1] = f2tf(pb[h].y);
            Bs[buf][bRow][bCol+h*4+2] = f2tf(pb[h].z);
            Bs[buf][bRow][bCol+h*4+3] = f2tf(pb[h].w);
        }
    };
    auto comp = [&](int buf) {
        #pragma unroll
        for (int ks = 0; ks < 2; ks++) {
            uint32_t af[4][4], bf[4][2];
            #pragma unroll
            for (int mi = 0; mi < 4; mi++) {
                int m = wm + mi*16;
                af[mi][0] = As[buf][ks*8+kt  ][m+g  ];
                af[mi][1] = As[buf][ks*8+kt  ][m+g+8];
                af[mi][2] = As[buf][ks*8+kt+4][m+g  ];
                af[mi][3] = As[buf][ks*8+kt+4][m+g+8];
            }
            #pragma unroll
            for (int nj = 0; nj < 4; nj++) {
                int n = wn + nj*8;
                bf[nj][0] = Bs[buf][ks*8+kt  ][n+g];
                bf[nj][1] = Bs[buf][ks*8+kt+4][n+g];
            }
            #pragma unroll
            for (int mi = 0; mi < 4; mi++)
                #pragma unroll
                for (int nj = 0; nj < 4; nj++) mma8(acc[mi][nj], af[mi], bf[nj]);
        }
    };
    const int nIter = (K + 15) >> 4;
    loadT(0); storeT(0); __syncthreads();
    for (int t = 1; t < nIter; t++) {
        loadT(t*16);
        comp((t-1) & 1);
        storeT(t & 1);
        __syncthreads();
    }
    comp((nIter-1) & 1);
    #pragma unroll
    for (int mi = 0; mi < 4; mi++)
        #pragma unroll
        for (int nj = 0; nj < 4; nj++)
            #pragma unroll
            for (int r = 0; r < 4; r++) {
                int gm = rowBase + wm + mi*16 + g + (r>>1)*8;
                int gn = colBase + wn + nj*8 + kt*2 + (r&1);
                if (gm < M && gn < N) C[(size_t)gm*N + gn] = acc[mi][nj][r];
            }
}

// ---------------- BN / pool / head ----------------
__global__ void k_x0_bn(const float* __restrict__ x, const float* __restrict__ g,
                        const float* __restrict__ be, float* __restrict__ z)
{
    int r = blockIdx.x;
    int c = r + threadIdx.x;
    if (c >= FN) return;
    long j = (long)r*FN - (long)r*(r-1)/2 + (c - r);
    long zi = (j & ~7L) + 2*(j & 3) + ((j >> 2) & 1);
    float s = 0.f, ss = 0.f;
    for (int b = 0; b < BGRAPH; b++) {
        float v = x[((size_t)(b*FN + r))*FN + c];
        s += v; ss += v*v;
    }
    float m = s*(1.f/BGRAPH);
    float var = ss*(1.f/BGRAPH) - m*m;
    float sc = rsqrtf(var + EPSV)*g[j];
    float bb = be[j];
    for (int b = 0; b < BGRAPH; b++) {
        float v = x[((size_t)(b*FN + r))*FN + c];
        z[(size_t)b*ZP + zi] = rndtf((v - m)*sc + bb);
    }
}
__global__ void k_pool(const __half* __restrict__ x1, const __half* __restrict__ x2,
                       const __half* __restrict__ x3, float* __restrict__ hp)
{
    int b = blockIdx.x, l = blockIdx.y, k = threadIdx.x;   // k = storage pos
    const __half* base = (l==0 ? x1 : l==1 ? x2 : x3) + (size_t)b*FN*CCH + k;
    float s0=0.f, s1=0.f, s2=0.f, s3=0.f;
    #pragma unroll 1
    for (int n = 0; n < FN; n += 4) {
        s0 += __half2float(base[(size_t)(n+0)*CCH]);
        s1 += __half2float(base[(size_t)(n+1)*CCH]);
        s2 += __half2float(base[(size_t)(n+2)*CCH]);
        s3 += __half2float(base[(size_t)(n+3)*CCH]);
    }
    int oc = (k & ~15) + orig16p(k & 15);   // original channel
    hp[b*384 + l*CCH + oc] = (s0+s1+s2+s3)*(1.0f/FN);
}
__global__ void k_bn_pool(const float* __restrict__ hp, const float* __restrict__ g,
                          const float* __restrict__ be, float* __restrict__ z)
{
    int j = blockIdx.x*blockDim.x + threadIdx.x;
    if (j >= 396) return;
    long cg2 = (long)TRI + j;
    long zi = (cg2 & ~7L) + 2*(cg2 & 3) + ((cg2 >> 2) & 1);
    if (j >= 384) {
        for (int b = 0; b < BGRAPH; b++) z[(size_t)b*ZP + zi] = 0.f;
        return;
    }
    float s = 0.f, ss = 0.f;
    for (int b = 0; b < BGRAPH; b++) { float v = hp[b*384 + j]; s += v; ss += v*v; }
    float m = s*(1.f/BGRAPH);
    float var = ss*(1.f/BGRAPH) - m*m;
    float sc = rsqrtf(var + EPSV)*g[j];
    float bb = be[j];
    for (int b = 0; b < BGRAPH; b++)
        z[(size_t)b*ZP + zi] = rndtf((hp[b*384 + j] - m)*sc + bb);
}
__global__ void k_bn_relu(const float* __restrict__ X, const float* __restrict__ bias,
                          const float* __restrict__ gam, const float* __restrict__ bet,
                          float* __restrict__ Y, int ncols)
{
    int col = blockIdx.x, t = threadIdx.x;
    float v = X[t*ncols + col] + bias[col];
    float s = v, ss = v*v;
    #pragma unroll
    for (int o = 16; o > 0; o >>= 1) {
        s  += __shfl_down_sync(0xffffffffu, s,  o);
        ss += __shfl_down_sync(0xffffffffu, ss, o);
    }
    __shared__ float ws[4], wss[4];
    __shared__ float sm, sscale;
    int wid = t >> 5, lane = t & 31;
    if (lane == 0) { ws[wid] = s; wss[wid] = ss; }
    __syncthreads();
    if (t == 0) {
        float S = ws[0]+ws[1]+ws[2]+ws[3];
        float SS = wss[0]+wss[1]+wss[2]+wss[3];
        float m = S*(1.f/BGRAPH);
        sm = m; sscale = rsqrtf(SS*(1.f/BGRAPH) - m*m + EPSV);
    }
    __syncthreads();
    float o = (v - sm)*sscale*gam[col] + bet[col];
    Y[t*ncols + col] = fmaxf(o, 0.f);
}
__global__ void k_head(const float* __restrict__ a3, const float* __restrict__ W4,
                       const float* __restrict__ b4, float* __restrict__ out)
{
    int b = blockIdx.x, lane = threadIdx.x;
    float s0 = 0.f, s1 = 0.f;
    for (int i = lane; i < H2; i += 32) {
        float v = a3[b*H2 + i];
        s0 = fmaf(v, W4[i*2+0], s0);
        s1 = fmaf(v, W4[i*2+1], s1);
    }
    #pragma unroll
    for (int o = 16; o > 0; o >>= 1) {
        s0 += __shfl_down_sync(0xffffffffu, s0, o);
        s1 += __shfl_down_sync(0xffffffffu, s1, o);
    }
    if (lane == 0) {
        float l0 = s0 + b4[0], l1 = s1 + b4[1];
        float m = fmaxf(l0, l1);
        float lse = m + logf(expf(l0-m) + expf(l1-m));
        out[b*2+0] = l0 - lse;
        out[b*2+1] = l1 - lse;
    }
}

// ---------------- launch ----------------
extern "C" void kernel_launch(void* const* d_in, const int* in_sizes, int n_in,
                              void* d_out, int out_size)
{
    const float* x    = (const float*)d_in[0];
    const int*   esrc = (const int*)d_in[1];
    const int*   edst = (const int*)d_in[2];
    const float* Wc1  = (const float*)d_in[4];
    const float* bc1  = (const float*)d_in[5];
    const float* Wc2  = (const float*)d_in[6];
    const float* bc2  = (const float*)d_in[7];
    const float* Wc3  = (const float*)d_in[8];
    const float* bc3  = (const float*)d_in[9];
    const float* bn_g = (const float*)d_in[10];
    const float* bn_b = (const float*)d_in[11];
    const float* bnh_g= (const float*)d_in[12];
    const float* bnh_b= (const float*)d_in[13];
    const float* W1   = (const float*)d_in[14];
    const float* b1   = (const float*)d_in[15];
    const float* g1   = (const float*)d_in[16];
    const float* be1  = (const float*)d_in[17];
    const float* W2   = (const float*)d_in[18];
    const float* b2   = (const float*)d_in[19];
    const float* g2   = (const float*)d_in[20];
    const float* be2  = (const float*)d_in[21];
    const float* W3   = (const float*)d_in[22];
    const float* b3   = (const float*)d_in[23];
    const float* g3   = (const float*)d_in[24];
    const float* be3  = (const float*)d_in[25];
    const float* W4   = (const float*)d_in[26];
    const float* b4   = (const float*)d_in[27];
    float* out = (float*)d_out;

    const int DSMH = 3*12288*2;   // 73728 B (fp16 GEMM, 3 stages)
    const int DSMZ = 2*10240*4;   // 81920 B (tf32 zW1)
    cudaFuncSetAttribute(gkh<0>, cudaFuncAttributeMaxDynamicSharedMemorySize, DSMH);
    cudaFuncSetAttribute(gkh<1>, cudaFuncAttributeMaxDynamicSharedMemorySize, DSMH);
    cudaFuncSetAttribute(gkz,    cudaFuncAttributeMaxDynamicSharedMemorySize, DSMZ);

    void *pDinv, *pA, *pAh, *pXh, *pHh, *pX1, *pX2, *pX3, *pZ, *pHp, *pA1, *pA2, *pA3;
    cudaGetSymbolAddress(&pDinv, g_dinv);
    cudaGetSymbolAddress(&pA,   g_A);
    cudaGetSymbolAddress(&pAh,  g_Ah);
    cudaGetSymbolAddress(&pXh,  g_xh);
    cudaGetSymbolAddress(&pHh,  g_hh);
    cudaGetSymbolAddress(&pX1,  g_x1h);
    cudaGetSymbolAddress(&pX2,  g_x2h);
    cudaGetSymbolAddress(&pX3,  g_x3h);
    cudaGetSymbolAddress(&pZ,   g_z);
    cudaGetSymbolAddress(&pHp,  g_hpool);
    cudaGetSymbolAddress(&pA1,  g_a1);
    cudaGetSymbolAddress(&pA2,  g_a2);
    cudaGetSymbolAddress(&pA3,  g_a3);

    void *pWh; cudaGetSymbolAddress(&pWh, g_wh);
    const __half* wh = (const __half*)pWh;
    const __half* xh = (const __half*)pXh;
    const __half* Ah = (const __half*)pAh;
    const __half* hh = (const __half*)pHh;

    // launch order: first fp16 GEMM at index 6 (empirical ncu capture slot)
    cudaMemsetAsync(pHh, 0, (size_t)BGRAPH*CCH*AP*2, 0);             // 0
    cudaMemsetAsync(pDinv, 0, (size_t)NNODE*4, 0);                   // 1
    cudaMemsetAsync(pA, 0, (size_t)BGRAPH*AP*AP*4, 0);               // 2
    k_count_deg<<<(NEDGE+255)/256, 256>>>(edst);                     // 3
    k_prep<<<(3*CCH*(AP/16)+255)/256, 256>>>(Wc1, Wc2, Wc3);         // 4
    k_xh<<<(NNODE*(AP/16)+255)/256, 256>>>(x);                       // 5
    gkh<0><<<dim3(360,1), 256, DSMH>>>(xh, wh, nullptr, nullptr,     // 6 <- ncu
                                       AP, AP, NNODE, AP);
    k_make_dinv<<<(NNODE+255)/256, 256>>>();                         // 7
    k_build<<<(NEDGE+NNODE+255)/256, 256>>>(esrc, edst);             // 8
    k_convA<<<2048, 256>>>();                                        // 9

    gkh<1><<<dim3(3,BGRAPH), 256, DSMH>>>(Ah, hh, bc1, (__half*)pX1, AP, AP, FN, AP);
    gkh<0><<<dim3(360,1), 256, DSMH>>>((const __half*)pX1, wh + (size_t)CCH*AP, nullptr, nullptr,
                                       CCH, AP, NNODE, CCH);
    gkh<1><<<dim3(3,BGRAPH), 256, DSMH>>>(Ah, hh, bc2, (__half*)pX2, AP, AP, FN, AP);
    gkh<0><<<dim3(360,1), 256, DSMH>>>((const __half*)pX2, wh + (size_t)2*CCH*AP, nullptr, nullptr,
                                       CCH, AP, NNODE, CCH);
    gkh<1><<<dim3(3,BGRAPH), 256, DSMH>>>(Ah, hh, bc3, (__half*)pX3, AP, AP, FN, AP);

    // features
    k_x0_bn<<<FN, 384>>>(x, bn_g, bn_b, (float*)pZ);
    k_pool<<<dim3(BGRAPH,3), CCH>>>((const __half*)pX1, (const __half*)pX2,
                                    (const __half*)pX3, (float*)pHp);
    k_bn_pool<<<1, 512>>>((const float*)pHp, bnh_g, bnh_b, (float*)pZ);

    // MLP head (tf32 path unchanged)
    cudaMemsetAsync(pA1, 0, (size_t)BGRAPH*H1*4, 0);
    gkz<<<dim3(1,4,64), 256, DSMZ>>>((const float*)pZ, W1, (float*)pA1, ZP, H1, ZP, D1, 1024);
    k_bn_relu<<<H1, 128>>>((const float*)pA1, b1, g1, be1, (float*)pA1, H1);
    mmak<<<dim3(1,2), 256>>>((const float*)pA1, W2, (float*)pA2, BGRAPH, H2, H1);
    k_bn_relu<<<H2, 128>>>((const float*)pA2, b2, g2, be2, (float*)pA2, H2);
    mmak<<<dim3(1,2), 256>>>((const float*)pA2, W3, (float*)pA3, BGRAPH, H2, H2);
    k_bn_relu<<<H2, 128>>>((const float*)pA3, b3, g3, be3, (float*)pA3, H2);
    k_head<<<BGRAPH, 32>>>((const float*)pA3, W4, b4, out);
}